// round 5
// baseline (speedup 1.0000x reference)
#include <cuda_runtime.h>
#include <math.h>

#define Bz   64
#define Tt   128
#define TM1  127
#define Vv   10000
#define Ee   300
#define Hh   1024
#define G4   4096
#define MROWS (TM1*Bz)   // 8128
#define GRID_REC 128

typedef unsigned long long ull;

// ---------------- scratch (device globals; no allocs allowed) ----------------
__device__ float g_xw[(size_t)MROWS * G4];     // precomputed x@w_ih0 + b0, layout (t,b,4H)
__device__ float g_h1all[(size_t)MROWS * Hh];  // all h1 states, layout (t,b,H)
__device__ float g_h0[2][Bz * Hh];             // ping-pong layer0 h state
__device__ float g_h1[2][Bz * Hh];             // ping-pong layer1 h state
__device__ float g_c0[Bz * Hh];
__device__ float g_c1[Bz * Hh];
__device__ float g_rowloss[MROWS];
__device__ unsigned g_barcnt;

// ---------------- f32x2 packed-FMA helpers (sm_100+) ----------------
__device__ __forceinline__ ull pk2(float x, float y) {
    ull r; asm("mov.b64 %0, {%1,%2};" : "=l"(r) : "f"(x), "f"(y)); return r;
}
__device__ __forceinline__ ull fma2(ull a, ull b, ull c) {
    ull d; asm("fma.rn.f32x2 %0, %1, %2, %3;" : "=l"(d) : "l"(a), "l"(b), "l"(c)); return d;
}
__device__ __forceinline__ float2 upk(ull v) {
    float2 f; asm("mov.b64 {%0,%1}, %2;" : "=f"(f.x), "=f"(f.y) : "l"(v)); return f;
}
__device__ __forceinline__ float sigf(float x) { return 1.0f / (1.0f + expf(-x)); }

// grid-wide epoch barrier (all GRID_REC blocks co-resident: 128 <= #SMs)
__device__ __forceinline__ void gbar(unsigned target) {
    __syncthreads();
    if (threadIdx.x == 0) {
        __threadfence();                       // release: make my writes visible at L2
        atomicAdd(&g_barcnt, 1u);
        unsigned v;
        do {
            asm volatile("ld.acquire.gpu.u32 %0, [%1];" : "=r"(v) : "l"(&g_barcnt));
        } while (v < target);
    }
    __syncthreads();
}

// ---------------- init states ----------------
__global__ void k_init() {
    int i = blockIdx.x * blockDim.x + threadIdx.x;
    if (i < Bz * Hh) {
        g_h0[0][i] = 0.f; g_h1[0][i] = 0.f;
        g_c0[i] = 0.f;    g_c1[i] = 0.f;
    }
    if (i == 0) g_barcnt = 0u;
}

// ---------------- K2: xW = gather(emb) @ w_ih0 + b0 (unchanged) ----------------
__global__ __launch_bounds__(256) void k_xw(const int* __restrict__ sent,
                                            const float* __restrict__ wordvec,
                                            const float* __restrict__ wih0,
                                            const float* __restrict__ b0) {
    __shared__ float As[8][128];
    __shared__ float Bs[8][128];
    __shared__ int stok[128];

    int tid = threadIdx.x;
    int n0 = blockIdx.x * 128;
    int m0 = blockIdx.y * 128;

    if (tid < 128) {
        int m = m0 + tid;
        int mc = (m < MROWS) ? m : (MROWS - 1);
        int t = mc >> 6, b = mc & 63;
        stok[tid] = sent[b * Tt + t];
    }
    __syncthreads();

    int tx = tid & 15, ty = tid >> 4;
    ull acc[8][4];
#pragma unroll
    for (int i = 0; i < 8; i++)
#pragma unroll
        for (int j = 0; j < 4; j++) acc[i][j] = 0ULL;

    for (int k0 = 0; k0 < Ee; k0 += 8) {
#pragma unroll
        for (int p = 0; p < 4; p++) {
            int idx = tid + p * 256;
            int r = idx & 127, kk = idx >> 7;
            int k = k0 + kk;
            As[kk][r] = (k < Ee) ? wordvec[(size_t)stok[r] * Ee + k] : 0.f;
            Bs[kk][r] = (k < Ee) ? wih0[(size_t)k * G4 + n0 + r] : 0.f;
        }
        __syncthreads();
#pragma unroll
        for (int kk = 0; kk < 8; kk++) {
            ull bf[4];
#pragma unroll
            for (int j = 0; j < 4; j++) bf[j] = *(const ull*)&Bs[kk][32 * j + 2 * tx];
#pragma unroll
            for (int i = 0; i < 8; i++) {
                float a = As[kk][ty + 16 * i];
                ull a2 = pk2(a, a);
#pragma unroll
                for (int j = 0; j < 4; j++) acc[i][j] = fma2(a2, bf[j], acc[i][j]);
            }
        }
        __syncthreads();
    }

#pragma unroll
    for (int i = 0; i < 8; i++) {
        int m = m0 + ty + 16 * i;
        if (m >= MROWS) continue;
        float* orow = g_xw + (size_t)m * G4 + n0;
#pragma unroll
        for (int j = 0; j < 4; j++) {
            float2 v = upk(acc[i][j]);
            int c = 32 * j + 2 * tx;
            orow[c]     = v.x + b0[n0 + c];
            orow[c + 1] = v.y + b0[n0 + c + 1];
        }
    }
}

// ---------------- K3: persistent fused recurrence ----------------
// 128 blocks x 256 threads; block owns 8 hidden units j0=bid*8 (32 gate cols).
// Rowpair-packed f32x2 GEMM: tile 64(batch) x 32(gatecols), chunks of 32 k,
// double-buffered smem w/ register prefetch; 2 grid barriers per step.
__global__ __launch_bounds__(256) void k_rec(const float* __restrict__ whh0,
                                             const float* __restrict__ wih1,
                                             const float* __restrict__ whh1,
                                             const float* __restrict__ b1) {
    __shared__ __align__(16) float sh_h[2][32][68];
    __shared__ __align__(16) ull   sh_w[2][32][32];
    __shared__ __align__(16) float sg[64][33];

    const int tid = threadIdx.x;
    const int j0  = blockIdx.x * 8;
    const int tx  = tid & 15, ty = tid >> 4;        // compute map
    const int fb  = tid >> 2, fq = tid & 3;         // h fill: batch, k-quarter
    const int fkk = tid >> 3;                       // w fill: kk in chunk
    const int fg  = (tid & 7) >> 1, fh = tid & 1;   // w fill: gate, half
    const int wcol = fg * Hh + j0 + fh * 4;         // gmem col base
    const int wsc  = fg * 8 + fh * 4;               // smem col base

    unsigned tgt = 0;

    for (int t = 0; t < TM1; t++) {
        const int pp = t & 1;

        // ================= phase A: layer0 =================
        {
            const float* hsrc = g_h0[pp];
            ull a00 = 0, a10 = 0, a01 = 0, a11 = 0;
            float4 ph0, ph1, pw;

            auto sts = [&](int b2) {
                sh_h[b2][fq * 8 + 0][fb] = ph0.x; sh_h[b2][fq * 8 + 1][fb] = ph0.y;
                sh_h[b2][fq * 8 + 2][fb] = ph0.z; sh_h[b2][fq * 8 + 3][fb] = ph0.w;
                sh_h[b2][fq * 8 + 4][fb] = ph1.x; sh_h[b2][fq * 8 + 5][fb] = ph1.y;
                sh_h[b2][fq * 8 + 6][fb] = ph1.z; sh_h[b2][fq * 8 + 7][fb] = ph1.w;
                ull* wsp = &sh_w[b2][fkk][wsc];
                wsp[0] = pk2(pw.x, pw.x); wsp[1] = pk2(pw.y, pw.y);
                wsp[2] = pk2(pw.z, pw.z); wsp[3] = pk2(pw.w, pw.w);
            };
            auto comp = [&](int b2) {
#pragma unroll
                for (int kk = 0; kk < 32; kk++) {
                    ulonglong2 hA = *(const ulonglong2*)&sh_h[b2][kk][4 * ty];
                    ulonglong2 wB = *(const ulonglong2*)&sh_w[b2][kk][2 * tx];
                    a00 = fma2(hA.x, wB.x, a00);
                    a10 = fma2(hA.y, wB.x, a10);
                    a01 = fma2(hA.x, wB.y, a01);
                    a11 = fma2(hA.y, wB.y, a11);
                }
            };

            ph0 = __ldcg((const float4*)(hsrc + fb * Hh + fq * 8));
            ph1 = __ldcg((const float4*)(hsrc + fb * Hh + fq * 8 + 4));
            pw  = __ldg ((const float4*)(whh0 + (size_t)fkk * G4 + wcol));
            int buf = 0;
            sts(buf);
            __syncthreads();
            const int NC = Hh / 32;
            for (int c = 0; c < NC; c++) {
                if (c + 1 < NC) {
                    int kb = (c + 1) * 32;
                    ph0 = __ldcg((const float4*)(hsrc + fb * Hh + kb + fq * 8));
                    ph1 = __ldcg((const float4*)(hsrc + fb * Hh + kb + fq * 8 + 4));
                    pw  = __ldg ((const float4*)(whh0 + (size_t)(kb + fkk) * G4 + wcol));
                }
                comp(buf);
                if (c + 1 < NC) sts(buf ^ 1);
                __syncthreads();
                buf ^= 1;
            }
            // stage to sg
            {
                float2 v;
                v = upk(a00); sg[4 * ty + 0][2 * tx]     = v.x; sg[4 * ty + 1][2 * tx]     = v.y;
                v = upk(a10); sg[4 * ty + 2][2 * tx]     = v.x; sg[4 * ty + 3][2 * tx]     = v.y;
                v = upk(a01); sg[4 * ty + 0][2 * tx + 1] = v.x; sg[4 * ty + 1][2 * tx + 1] = v.y;
                v = upk(a11); sg[4 * ty + 2][2 * tx + 1] = v.x; sg[4 * ty + 3][2 * tx + 1] = v.y;
            }
            __syncthreads();
            // cell update (block owns units j0..j0+7, all 64 batches)
            const float* xwbase = g_xw + (size_t)t * Bz * G4;
#pragma unroll
            for (int e = 0; e < 2; e++) {
                int idx = tid + e * 256;
                int bb = idx & 63, jj = idx >> 6;
                const float* xwr = xwbase + (size_t)bb * G4 + j0 + jj;
                float iv = sg[bb][jj]      + xwr[0];
                float fv = sg[bb][8 + jj]  + xwr[Hh];
                float gv = sg[bb][16 + jj] + xwr[2 * Hh];
                float ov = sg[bb][24 + jj] + xwr[3 * Hh];
                int hi = bb * Hh + j0 + jj;
                float co = g_c0[hi];
                float cn = sigf(fv) * co + sigf(iv) * tanhf(gv);
                float hn = sigf(ov) * tanhf(cn);
                g_c0[hi] = cn;
                g_h0[pp ^ 1][hi] = hn;
            }
        }
        tgt += GRID_REC; gbar(tgt);

        // ================= phase B: layer1 (K=2048) =================
        {
            const float* h0n = g_h0[pp ^ 1];
            const float* h1o = g_h1[pp];
            ull a00 = 0, a10 = 0, a01 = 0, a11 = 0;
            float4 ph0, ph1, pw;

            auto sts = [&](int b2) {
                sh_h[b2][fq * 8 + 0][fb] = ph0.x; sh_h[b2][fq * 8 + 1][fb] = ph0.y;
                sh_h[b2][fq * 8 + 2][fb] = ph0.z; sh_h[b2][fq * 8 + 3][fb] = ph0.w;
                sh_h[b2][fq * 8 + 4][fb] = ph1.x; sh_h[b2][fq * 8 + 5][fb] = ph1.y;
                sh_h[b2][fq * 8 + 6][fb] = ph1.z; sh_h[b2][fq * 8 + 7][fb] = ph1.w;
                ull* wsp = &sh_w[b2][fkk][wsc];
                wsp[0] = pk2(pw.x, pw.x); wsp[1] = pk2(pw.y, pw.y);
                wsp[2] = pk2(pw.z, pw.z); wsp[3] = pk2(pw.w, pw.w);
            };
            auto comp = [&](int b2) {
#pragma unroll
                for (int kk = 0; kk < 32; kk++) {
                    ulonglong2 hA = *(const ulonglong2*)&sh_h[b2][kk][4 * ty];
                    ulonglong2 wB = *(const ulonglong2*)&sh_w[b2][kk][2 * tx];
                    a00 = fma2(hA.x, wB.x, a00);
                    a10 = fma2(hA.y, wB.x, a10);
                    a01 = fma2(hA.x, wB.y, a01);
                    a11 = fma2(hA.y, wB.y, a11);
                }
            };

            ph0 = __ldcg((const float4*)(h0n + fb * Hh + fq * 8));
            ph1 = __ldcg((const float4*)(h0n + fb * Hh + fq * 8 + 4));
            pw  = __ldg ((const float4*)(wih1 + (size_t)fkk * G4 + wcol));
            int buf = 0;
            sts(buf);
            __syncthreads();
            const int NC = 2 * Hh / 32;
            for (int c = 0; c < NC; c++) {
                if (c + 1 < NC) {
                    int kn = (c + 1) * 32;
                    const float* hs = (kn < Hh) ? h0n : h1o;
                    const float* wg = (kn < Hh) ? wih1 : whh1;
                    int kb = kn & (Hh - 1);
                    ph0 = __ldcg((const float4*)(hs + fb * Hh + kb + fq * 8));
                    ph1 = __ldcg((const float4*)(hs + fb * Hh + kb + fq * 8 + 4));
                    pw  = __ldg ((const float4*)(wg + (size_t)(kb + fkk) * G4 + wcol));
                }
                comp(buf);
                if (c + 1 < NC) sts(buf ^ 1);
                __syncthreads();
                buf ^= 1;
            }
            {
                float2 v;
                v = upk(a00); sg[4 * ty + 0][2 * tx]     = v.x; sg[4 * ty + 1][2 * tx]     = v.y;
                v = upk(a10); sg[4 * ty + 2][2 * tx]     = v.x; sg[4 * ty + 3][2 * tx]     = v.y;
                v = upk(a01); sg[4 * ty + 0][2 * tx + 1] = v.x; sg[4 * ty + 1][2 * tx + 1] = v.y;
                v = upk(a11); sg[4 * ty + 2][2 * tx + 1] = v.x; sg[4 * ty + 3][2 * tx + 1] = v.y;
            }
            __syncthreads();
#pragma unroll
            for (int e = 0; e < 2; e++) {
                int idx = tid + e * 256;
                int bb = idx & 63, jj = idx >> 6;
                int col = j0 + jj;
                float iv = sg[bb][jj]      + b1[col];
                float fv = sg[bb][8 + jj]  + b1[Hh + col];
                float gv = sg[bb][16 + jj] + b1[2 * Hh + col];
                float ov = sg[bb][24 + jj] + b1[3 * Hh + col];
                int hi = bb * Hh + col;
                float co = g_c1[hi];
                float cn = sigf(fv) * co + sigf(iv) * tanhf(gv);
                float hn = sigf(ov) * tanhf(cn);
                g_c1[hi] = cn;
                g_h1[pp ^ 1][hi] = hn;
                g_h1all[((size_t)t * Bz + bb) * Hh + col] = hn;
            }
        }
        tgt += GRID_REC; gbar(tgt);
    }
}

// ---------------- K4: logits = h1_all @ w_out + b_out (rowpair f32x2) ----------
// tile 128(m) x 128(n), 256 thr, thread: 16 rows (8 rowpairs) x 4 cols = 32 ull acc
__global__ __launch_bounds__(256, 2) void k_logits(const float* __restrict__ wout,
                                                   const float* __restrict__ bout,
                                                   float* __restrict__ out) {
    __shared__ __align__(16) float As[8][132];
    __shared__ __align__(16) ull   Bd[8][128];
    __shared__ int aoff[128];

    int tid = threadIdx.x;
    int n0 = blockIdx.x * 128;
    int m0 = blockIdx.y * 128;

    if (tid < 128) {
        int m = m0 + tid;
        int mc = (m < MROWS) ? m : (MROWS - 1);
        int b = mc / 127, t = mc - b * 127;
        aoff[tid] = t * Bz + b;
    }
    __syncthreads();

    int tx = tid & 31, wy = tid >> 5;
    int ar = tid >> 1, akq = tid & 1;
    int bkk = tid >> 5, bc = (tid & 31) * 4;
    bool bok = (n0 + bc + 3 < Vv);

    ull acc[8][4];
#pragma unroll
    for (int p = 0; p < 8; p++)
#pragma unroll
        for (int j = 0; j < 4; j++) acc[p][j] = 0ULL;

    for (int k0 = 0; k0 < Hh; k0 += 8) {
        float4 av = __ldg((const float4*)(g_h1all + (size_t)aoff[ar] * Hh + k0 + akq * 4));
        float4 bv = make_float4(0.f, 0.f, 0.f, 0.f);
        if (bok) {
            bv = __ldg((const float4*)(wout + (size_t)(k0 + bkk) * Vv + n0 + bc));
        } else {
            const float* wr = wout + (size_t)(k0 + bkk) * Vv;
            if (n0 + bc + 0 < Vv) bv.x = wr[n0 + bc + 0];
            if (n0 + bc + 1 < Vv) bv.y = wr[n0 + bc + 1];
            if (n0 + bc + 2 < Vv) bv.z = wr[n0 + bc + 2];
            if (n0 + bc + 3 < Vv) bv.w = wr[n0 + bc + 3];
        }
        __syncthreads();
        As[akq * 4 + 0][ar] = av.x; As[akq * 4 + 1][ar] = av.y;
        As[akq * 4 + 2][ar] = av.z; As[akq * 4 + 3][ar] = av.w;
        Bd[bkk][bc + 0] = pk2(bv.x, bv.x); Bd[bkk][bc + 1] = pk2(bv.y, bv.y);
        Bd[bkk][bc + 2] = pk2(bv.z, bv.z); Bd[bkk][bc + 3] = pk2(bv.w, bv.w);
        __syncthreads();
#pragma unroll
        for (int kk = 0; kk < 8; kk++) {
            ulonglong2 A0 = *(const ulonglong2*)&As[kk][wy * 16 + 0];
            ulonglong2 A1 = *(const ulonglong2*)&As[kk][wy * 16 + 4];
            ulonglong2 A2 = *(const ulonglong2*)&As[kk][wy * 16 + 8];
            ulonglong2 A3 = *(const ulonglong2*)&As[kk][wy * 16 + 12];
            ull hr[8] = {A0.x, A0.y, A1.x, A1.y, A2.x, A2.y, A3.x, A3.y};
#pragma unroll
            for (int j = 0; j < 4; j++) {
                ull w = Bd[kk][tx + 32 * j];
#pragma unroll
                for (int p = 0; p < 8; p++) acc[p][j] = fma2(hr[p], w, acc[p][j]);
            }
        }
    }

#pragma unroll
    for (int p = 0; p < 8; p++) {
        int m = m0 + wy * 16 + 2 * p;
#pragma unroll
        for (int j = 0; j < 4; j++) {
            int n = n0 + tx + 32 * j;
            if (n < Vv) {
                float2 v = upk(acc[p][j]);
                float bo = bout[n];
                if (m < MROWS)     out[1 + (size_t)m * Vv + n]       = v.x + bo;
                if (m + 1 < MROWS) out[1 + (size_t)(m + 1) * Vv + n] = v.y + bo;
            }
        }
    }
}

// ---------------- K5: per-row log-softmax at gt; masked by PAD ----------------
__global__ __launch_bounds__(256) void k_rowloss(const float* __restrict__ out,
                                                 const int* __restrict__ sent) {
    __shared__ float red[256];
    int m = blockIdx.x;
    const float* row = out + 1 + (size_t)m * Vv;
    int tid = threadIdx.x;

    float mx = -3.4e38f;
    for (int v = tid; v < Vv; v += 256) mx = fmaxf(mx, row[v]);
    red[tid] = mx; __syncthreads();
    for (int s = 128; s > 0; s >>= 1) {
        if (tid < s) red[tid] = fmaxf(red[tid], red[tid + s]);
        __syncthreads();
    }
    mx = red[0]; __syncthreads();

    float sm = 0.f;
    for (int v = tid; v < Vv; v += 256) sm += expf(row[v] - mx);
    red[tid] = sm; __syncthreads();
    for (int s = 128; s > 0; s >>= 1) {
        if (tid < s) red[tid] += red[tid + s];
        __syncthreads();
    }

    if (tid == 0) {
        int b = m / 127, t = m - b * 127;
        int gt = sent[b * Tt + t + 1];
        float lp = 0.f;
        if (gt != 0) lp = row[gt] - mx - logf(red[0]);
        g_rowloss[m] = lp;
    }
}

// ---------------- K6: deterministic loss reduction ----------------
__global__ void k_loss(const int* __restrict__ length, float* __restrict__ out) {
    __shared__ float sb[64];
    int b = threadIdx.x;
    float a = 0.f;
    for (int t = 0; t < TM1; t++) a += g_rowloss[b * TM1 + t];
    sb[b] = -a / (float)length[b];
    __syncthreads();
    if (b == 0) {
        float s = 0.f;
        for (int i = 0; i < 64; i++) s += sb[i];
        out[0] = s;
    }
}

// ---------------- host ----------------
extern "C" void kernel_launch(void* const* d_in, const int* in_sizes, int n_in,
                              void* d_out, int out_size) {
    const int*   sent    = (const int*)d_in[0];
    const int*   length  = (const int*)d_in[1];
    const float* wordvec = (const float*)d_in[2];
    const float* wih0    = (const float*)d_in[3];
    const float* whh0    = (const float*)d_in[4];
    const float* b0      = (const float*)d_in[5];
    const float* wih1    = (const float*)d_in[6];
    const float* whh1    = (const float*)d_in[7];
    const float* b1      = (const float*)d_in[8];
    const float* wout    = (const float*)d_in[9];
    const float* bout    = (const float*)d_in[10];
    float* out = (float*)d_out;

    k_init<<<256, 256>>>();
    k_xw<<<dim3(G4 / 128, 64), 256>>>(sent, wordvec, wih0, b0);
    k_rec<<<GRID_REC, 256>>>(whh0, wih1, whh1, b1);
    k_logits<<<dim3((Vv + 127) / 128, (MROWS + 127) / 128), 256>>>(wout, bout, out);
    k_rowloss<<<MROWS, 256>>>(out, sent);
    k_loss<<<1, 64>>>(length, out);
}

// round 6
// speedup vs baseline: 1.0983x; 1.0983x over previous
#include <cuda_runtime.h>
#include <math.h>

#define Bz   64
#define Tt   128
#define TM1  127
#define Vv   10000
#define Ee   300
#define Hh   1024
#define G4   4096
#define MROWS (TM1*Bz)   // 8128
#define GRID_REC 128

typedef unsigned long long ull;

// ---------------- scratch (device globals; no allocs allowed) ----------------
__device__ float g_xw[(size_t)MROWS * G4];     // precomputed x@w_ih0 + b0, layout (t,b,4H)
__device__ float g_h1all[(size_t)MROWS * Hh];  // all h1 states, layout (t,b,H)
__device__ float g_h0[2][Bz * Hh];             // ping-pong layer0 h state
__device__ float g_h1[2][Bz * Hh];             // ping-pong layer1 h state
__device__ float g_rowloss[MROWS];
__device__ unsigned g_barcnt;

// ---------------- f32x2 packed-FMA helpers (sm_100+) ----------------
__device__ __forceinline__ ull pk2(float x, float y) {
    ull r; asm("mov.b64 %0, {%1,%2};" : "=l"(r) : "f"(x), "f"(y)); return r;
}
__device__ __forceinline__ ull fma2(ull a, ull b, ull c) {
    ull d; asm("fma.rn.f32x2 %0, %1, %2, %3;" : "=l"(d) : "l"(a), "l"(b), "l"(c)); return d;
}
__device__ __forceinline__ float2 upk(ull v) {
    float2 f; asm("mov.b64 {%0,%1}, %2;" : "=f"(f.x), "=f"(f.y) : "l"(v)); return f;
}
__device__ __forceinline__ float sigf(float x) { return 1.0f / (1.0f + expf(-x)); }

__device__ __forceinline__ unsigned smem_u32(const void* p) {
    unsigned a;
    asm("{ .reg .u64 t; cvta.to.shared.u64 t, %1; cvt.u32.u64 %0, t; }" : "=r"(a) : "l"(p));
    return a;
}
__device__ __forceinline__ void cp16(unsigned dst, const void* src) {
    asm volatile("cp.async.cg.shared.global [%0], [%1], 16;" :: "r"(dst), "l"(src));
}

// grid-wide epoch barrier (all GRID_REC blocks co-resident: 128 <= #SMs)
__device__ __forceinline__ void gbar(unsigned target) {
    __syncthreads();
    if (threadIdx.x == 0) {
        __threadfence();
        atomicAdd(&g_barcnt, 1u);
        unsigned v;
        do {
            asm volatile("ld.acquire.gpu.u32 %0, [%1];" : "=r"(v) : "l"(&g_barcnt));
        } while (v < target);
    }
    __syncthreads();
}

// ---------------- init states ----------------
__global__ void k_init() {
    int i = blockIdx.x * blockDim.x + threadIdx.x;
    if (i < Bz * Hh) {
        g_h0[0][i] = 0.f; g_h1[0][i] = 0.f;
    }
    if (i == 0) g_barcnt = 0u;
}

// ---------------- K2: xW = gather(emb) @ w_ih0 + b0 ----------------
__global__ __launch_bounds__(256) void k_xw(const int* __restrict__ sent,
                                            const float* __restrict__ wordvec,
                                            const float* __restrict__ wih0,
                                            const float* __restrict__ b0) {
    __shared__ float As[8][128];
    __shared__ float Bs[8][128];
    __shared__ int stok[128];

    int tid = threadIdx.x;
    int n0 = blockIdx.x * 128;
    int m0 = blockIdx.y * 128;

    if (tid < 128) {
        int m = m0 + tid;
        int mc = (m < MROWS) ? m : (MROWS - 1);
        int t = mc >> 6, b = mc & 63;
        stok[tid] = sent[b * Tt + t];
    }
    __syncthreads();

    int tx = tid & 15, ty = tid >> 4;
    ull acc[8][4];
#pragma unroll
    for (int i = 0; i < 8; i++)
#pragma unroll
        for (int j = 0; j < 4; j++) acc[i][j] = 0ULL;

    for (int k0 = 0; k0 < Ee; k0 += 8) {
#pragma unroll
        for (int p = 0; p < 4; p++) {
            int idx = tid + p * 256;
            int r = idx & 127, kk = idx >> 7;
            int k = k0 + kk;
            As[kk][r] = (k < Ee) ? wordvec[(size_t)stok[r] * Ee + k] : 0.f;
            Bs[kk][r] = (k < Ee) ? wih0[(size_t)k * G4 + n0 + r] : 0.f;
        }
        __syncthreads();
#pragma unroll
        for (int kk = 0; kk < 8; kk++) {
            ull bf[4];
#pragma unroll
            for (int j = 0; j < 4; j++) bf[j] = *(const ull*)&Bs[kk][32 * j + 2 * tx];
#pragma unroll
            for (int i = 0; i < 8; i++) {
                float a = As[kk][ty + 16 * i];
                ull a2 = pk2(a, a);
#pragma unroll
                for (int j = 0; j < 4; j++) acc[i][j] = fma2(a2, bf[j], acc[i][j]);
            }
        }
        __syncthreads();
    }

#pragma unroll
    for (int i = 0; i < 8; i++) {
        int m = m0 + ty + 16 * i;
        if (m >= MROWS) continue;
        float* orow = g_xw + (size_t)m * G4 + n0;
#pragma unroll
        for (int j = 0; j < 4; j++) {
            float2 v = upk(acc[i][j]);
            int c = 32 * j + 2 * tx;
            orow[c]     = v.x + b0[n0 + c];
            orow[c + 1] = v.y + b0[n0 + c + 1];
        }
    }
}

// ---------------- K3: persistent merged-phase recurrence ----------------
// Phase p computes layer0(t=p) and layer1(t=p-1); both consume h0[p-1] (shared
// h tile) and h1[p-2]. 512 threads = 2 k-split groups of 256. One grid barrier
// per phase. States c0/c1 live in smem.
#define SMEM_REC 150656
__global__ void __launch_bounds__(512) k_rec(const float* __restrict__ whh0,
                                             const float* __restrict__ wih1,
                                             const float* __restrict__ whh1,
                                             const float* __restrict__ b1) {
    extern __shared__ __align__(16) char smem[];
    // [g][buf][kk][b] h tile
    float (*SHH)[2][32][68] = (float (*)[2][32][68])(smem);
    // [g][buf][kk][col] dup'd weights (pass1: whh0 / pass2: whh1)
    ull   (*SW0)[2][32][34] = (ull (*)[2][32][34])(smem + 34816);
    // [g][buf][kk][col] dup'd wih1 (pass1 only)
    ull   (*SWI)[2][32][34] = (ull (*)[2][32][34])(smem + 69632);
    // gate partials: 0=A(g0 L0) 1=A2(g1 L0) 2=B(g1 L1) 3=B2(g0 L1)
    float (*SGD)[64][33]    = (float (*)[64][33])(smem + 104448);
    float (*SXW)[32]        = (float (*)[32])(smem + 138240);   // [64][32]
    float *SC0 = (float*)(smem + 146432);                        // [512]
    float *SC1 = SC0 + 512;                                      // [512]
    float *SB1 = SC1 + 512;                                      // [32]

    const int tid = threadIdx.x;
    const int g   = tid >> 8;          // k-split group
    const int f   = tid & 255;
    const int tx  = f & 15, ty = f >> 4;
    const int j0  = blockIdx.x * 8;

    // fill maps
    const int hb  = f & 63, kq0 = f >> 6;        // h fill: batch, k-quad (+4 for slot2)
    const int kkf = f >> 3;                      // w fill: kk
    const int c4  = (f & 7) * 4;                 // w fill: col group of 4
    const int wcol4 = ((c4 >> 3) << 10) + j0 + (c4 & 7);
    const int kg  = g * 512;                     // group k base

    // smem init
    SC0[tid < 512 ? tid : 0] = 0.f;  // tid always <512
    SC1[tid] = 0.f;
    if (tid < 32) SB1[tid] = b1[((tid >> 3) << 10) + j0 + (tid & 7)];
    __syncthreads();

    const unsigned sxw_base = smem_u32(&SXW[0][0]);

    auto sts_h = [&](int bf, const float* hs, int kbase) {
        float4 v0 = __ldcg((const float4*)(hs + hb * Hh + kbase + kq0 * 4));
        float4 v1 = __ldcg((const float4*)(hs + hb * Hh + kbase + kq0 * 4 + 16));
        float* col = &SHH[g][bf][0][hb];
        int r0 = kq0 * 4;
        col[(r0 + 0) * 68] = v0.x; col[(r0 + 1) * 68] = v0.y;
        col[(r0 + 2) * 68] = v0.z; col[(r0 + 3) * 68] = v0.w;
        int r1 = r0 + 16;
        col[(r1 + 0) * 68] = v1.x; col[(r1 + 1) * 68] = v1.y;
        col[(r1 + 2) * 68] = v1.z; col[(r1 + 3) * 68] = v1.w;
    };

    auto store8 = [&](float (*sg)[33], ull* a) {
        float2 v;
        v = upk(a[0]); sg[4*ty+0][2*tx]   = v.x; sg[4*ty+1][2*tx]   = v.y;
        v = upk(a[1]); sg[4*ty+2][2*tx]   = v.x; sg[4*ty+3][2*tx]   = v.y;
        v = upk(a[2]); sg[4*ty+0][2*tx+1] = v.x; sg[4*ty+1][2*tx+1] = v.y;
        v = upk(a[3]); sg[4*ty+2][2*tx+1] = v.x; sg[4*ty+3][2*tx+1] = v.y;
    };

    unsigned tgt = 0;

    for (int p = 0; p < 128; p++) {
        const int cur = p & 1, nxt = cur ^ 1;

        // prefetch xw[t=p] slice (64 x 32) via cp.async
        if (p < 127) {
            int b = tid >> 3, q = tid & 7;
            const float* src = g_xw + ((size_t)p * Bz + b) * G4
                               + ((q >> 1) << 10) + j0 + (q & 1) * 4;
            cp16(sxw_base + (unsigned)(b * 32 + q * 4) * 4u, src);
            asm volatile("cp.async.commit_group;");
        }

        ull a0[4] = {0,0,0,0}, a1[4] = {0,0,0,0};
        const float* h0src = g_h0[cur];

        // ================= pass1: h0 x (whh0, wih1) =================
        {
            float4 pw0 = __ldg((const float4*)(whh0 + (size_t)(kg + kkf) * G4 + wcol4));
            float4 pwi = __ldg((const float4*)(wih1 + (size_t)(kg + kkf) * G4 + wcol4));
            int buf = 0;
            sts_h(0, h0src, kg);
            {
                ulonglong2* d0 = (ulonglong2*)&SW0[g][0][kkf][c4];
                d0[0] = make_ulonglong2(pk2(pw0.x, pw0.x), pk2(pw0.y, pw0.y));
                d0[1] = make_ulonglong2(pk2(pw0.z, pw0.z), pk2(pw0.w, pw0.w));
                ulonglong2* d1 = (ulonglong2*)&SWI[g][0][kkf][c4];
                d1[0] = make_ulonglong2(pk2(pwi.x, pwi.x), pk2(pwi.y, pwi.y));
                d1[1] = make_ulonglong2(pk2(pwi.z, pwi.z), pk2(pwi.w, pwi.w));
            }
            __syncthreads();
            for (int c = 0; c < 16; c++) {
                if (c < 15) {
                    int kb = kg + (c + 1) * 32;
                    pw0 = __ldg((const float4*)(whh0 + (size_t)(kb + kkf) * G4 + wcol4));
                    pwi = __ldg((const float4*)(wih1 + (size_t)(kb + kkf) * G4 + wcol4));
                }
#pragma unroll
                for (int kk = 0; kk < 32; kk++) {
                    ulonglong2 hA = *(const ulonglong2*)&SHH[g][buf][kk][4 * ty];
                    ulonglong2 w0 = *(const ulonglong2*)&SW0[g][buf][kk][2 * tx];
                    ulonglong2 wi = *(const ulonglong2*)&SWI[g][buf][kk][2 * tx];
                    a0[0] = fma2(hA.x, w0.x, a0[0]); a0[1] = fma2(hA.y, w0.x, a0[1]);
                    a0[2] = fma2(hA.x, w0.y, a0[2]); a0[3] = fma2(hA.y, w0.y, a0[3]);
                    a1[0] = fma2(hA.x, wi.x, a1[0]); a1[1] = fma2(hA.y, wi.x, a1[1]);
                    a1[2] = fma2(hA.x, wi.y, a1[2]); a1[3] = fma2(hA.y, wi.y, a1[3]);
                }
                if (c < 15) {
                    int kb = kg + (c + 1) * 32;
                    sts_h(buf ^ 1, h0src, kb);
                    ulonglong2* d0 = (ulonglong2*)&SW0[g][buf ^ 1][kkf][c4];
                    d0[0] = make_ulonglong2(pk2(pw0.x, pw0.x), pk2(pw0.y, pw0.y));
                    d0[1] = make_ulonglong2(pk2(pw0.z, pw0.z), pk2(pw0.w, pw0.w));
                    ulonglong2* d1 = (ulonglong2*)&SWI[g][buf ^ 1][kkf][c4];
                    d1[0] = make_ulonglong2(pk2(pwi.x, pwi.x), pk2(pwi.y, pwi.y));
                    d1[1] = make_ulonglong2(pk2(pwi.z, pwi.z), pk2(pwi.w, pwi.w));
                }
                __syncthreads();
                buf ^= 1;
            }
        }

        // ================= pass2: h1[p-2] x whh1 (p>0) =================
        if (p > 0) {
            const float* h1src = g_h1[nxt];
            float4 pw0 = __ldg((const float4*)(whh1 + (size_t)(kg + kkf) * G4 + wcol4));
            int buf = 0;
            sts_h(0, h1src, kg);
            {
                ulonglong2* d0 = (ulonglong2*)&SW0[g][0][kkf][c4];
                d0[0] = make_ulonglong2(pk2(pw0.x, pw0.x), pk2(pw0.y, pw0.y));
                d0[1] = make_ulonglong2(pk2(pw0.z, pw0.z), pk2(pw0.w, pw0.w));
            }
            __syncthreads();
            for (int c = 0; c < 16; c++) {
                if (c < 15) {
                    int kb = kg + (c + 1) * 32;
                    pw0 = __ldg((const float4*)(whh1 + (size_t)(kb + kkf) * G4 + wcol4));
                }
#pragma unroll
                for (int kk = 0; kk < 32; kk++) {
                    ulonglong2 hA = *(const ulonglong2*)&SHH[g][buf][kk][4 * ty];
                    ulonglong2 w1 = *(const ulonglong2*)&SW0[g][buf][kk][2 * tx];
                    a1[0] = fma2(hA.x, w1.x, a1[0]); a1[1] = fma2(hA.y, w1.x, a1[1]);
                    a1[2] = fma2(hA.x, w1.y, a1[2]); a1[3] = fma2(hA.y, w1.y, a1[3]);
                }
                if (c < 15) {
                    int kb = kg + (c + 1) * 32;
                    sts_h(buf ^ 1, h1src, kb);
                    ulonglong2* d0 = (ulonglong2*)&SW0[g][buf ^ 1][kkf][c4];
                    d0[0] = make_ulonglong2(pk2(pw0.x, pw0.x), pk2(pw0.y, pw0.y));
                    d0[1] = make_ulonglong2(pk2(pw0.z, pw0.z), pk2(pw0.w, pw0.w));
                }
                __syncthreads();
                buf ^= 1;
            }
        }

        // ================= reduce + epilogues =================
        store8(SGD[g], a0);          // g0->SGD[0](L0), g1->SGD[1](L0)
        store8(SGD[3 - g], a1);      // g0->SGD[3](L1), g1->SGD[2](L1)
        if (p < 127) asm volatile("cp.async.wait_group 0;");
        __syncthreads();

        if (g == 0) {
            if (p < 127) {
#pragma unroll
                for (int e = 0; e < 2; e++) {
                    int idx = f + 256 * e;
                    int bb = idx & 63, jj = idx >> 6;
                    float iv = SGD[0][bb][jj]      + SGD[1][bb][jj]      + SXW[bb][jj];
                    float fv = SGD[0][bb][8 + jj]  + SGD[1][bb][8 + jj]  + SXW[bb][8 + jj];
                    float gv = SGD[0][bb][16 + jj] + SGD[1][bb][16 + jj] + SXW[bb][16 + jj];
                    float ov = SGD[0][bb][24 + jj] + SGD[1][bb][24 + jj] + SXW[bb][24 + jj];
                    float co = SC0[idx];
                    float cn = sigf(fv) * co + sigf(iv) * tanhf(gv);
                    float hn = sigf(ov) * tanhf(cn);
                    SC0[idx] = cn;
                    g_h0[nxt][bb * Hh + j0 + jj] = hn;
                }
            }
        } else {
            if (p > 0) {
                int t = p - 1;
#pragma unroll
                for (int e = 0; e < 2; e++) {
                    int idx = f + 256 * e;
                    int bb = idx & 63, jj = idx >> 6;
                    float iv = SGD[2][bb][jj]      + SGD[3][bb][jj]      + SB1[jj];
                    float fv = SGD[2][bb][8 + jj]  + SGD[3][bb][8 + jj]  + SB1[8 + jj];
                    float gv = SGD[2][bb][16 + jj] + SGD[3][bb][16 + jj] + SB1[16 + jj];
                    float ov = SGD[2][bb][24 + jj] + SGD[3][bb][24 + jj] + SB1[24 + jj];
                    float co = SC1[idx];
                    float cn = sigf(fv) * co + sigf(iv) * tanhf(gv);
                    float hn = sigf(ov) * tanhf(cn);
                    SC1[idx] = cn;
                    g_h1[cur][bb * Hh + j0 + jj] = hn;
                    g_h1all[((size_t)t * Bz + bb) * Hh + j0 + jj] = hn;
                }
            }
        }

        if (p < 127) { tgt += GRID_REC; gbar(tgt); }
    }
}

// ---------------- K4: logits = h1_all @ w_out + b_out (double-buffered) -------
__global__ __launch_bounds__(256, 2) void k_logits(const float* __restrict__ wout,
                                                   const float* __restrict__ bout,
                                                   float* __restrict__ out) {
    __shared__ __align__(16) float As[2][8][132];
    __shared__ __align__(16) ull   Bd[2][8][128];
    __shared__ int aoff[128];

    int tid = threadIdx.x;
    int n0 = blockIdx.x * 128;
    int m0 = blockIdx.y * 128;

    if (tid < 128) {
        int m = m0 + tid;
        int mc = (m < MROWS) ? m : (MROWS - 1);
        int b = mc / 127, t = mc - b * 127;
        aoff[tid] = t * Bz + b;
    }
    __syncthreads();

    int tx = tid & 31, wy = tid >> 5;
    int ar = tid >> 1, akq = tid & 1;
    int bkk = tid >> 5, bc = (tid & 31) * 4;
    bool bok = (n0 + bc + 3 < Vv);

    ull acc[8][4];
#pragma unroll
    for (int p = 0; p < 8; p++)
#pragma unroll
        for (int j = 0; j < 4; j++) acc[p][j] = 0ULL;

    auto ldA = [&](int k0) -> float4 {
        return __ldg((const float4*)(g_h1all + (size_t)aoff[ar] * Hh + k0 + akq * 4));
    };
    auto ldB = [&](int k0) -> float4 {
        float4 bv = make_float4(0.f, 0.f, 0.f, 0.f);
        if (bok) {
            bv = __ldg((const float4*)(wout + (size_t)(k0 + bkk) * Vv + n0 + bc));
        } else {
            const float* wr = wout + (size_t)(k0 + bkk) * Vv;
            if (n0 + bc + 0 < Vv) bv.x = wr[n0 + bc + 0];
            if (n0 + bc + 1 < Vv) bv.y = wr[n0 + bc + 1];
            if (n0 + bc + 2 < Vv) bv.z = wr[n0 + bc + 2];
            if (n0 + bc + 3 < Vv) bv.w = wr[n0 + bc + 3];
        }
        return bv;
    };
    auto sts = [&](int bf, float4 av, float4 bv) {
        As[bf][akq * 4 + 0][ar] = av.x; As[bf][akq * 4 + 1][ar] = av.y;
        As[bf][akq * 4 + 2][ar] = av.z; As[bf][akq * 4 + 3][ar] = av.w;
        Bd[bf][bkk][bc + 0] = pk2(bv.x, bv.x); Bd[bf][bkk][bc + 1] = pk2(bv.y, bv.y);
        Bd[bf][bkk][bc + 2] = pk2(bv.z, bv.z); Bd[bf][bkk][bc + 3] = pk2(bv.w, bv.w);
    };

    float4 av = ldA(0), bv = ldB(0);
    sts(0, av, bv);
    __syncthreads();
    int buf = 0;

    for (int k0 = 0; k0 < Hh; k0 += 8) {
        bool more = (k0 + 8 < Hh);
        if (more) { av = ldA(k0 + 8); bv = ldB(k0 + 8); }
#pragma unroll
        for (int kk = 0; kk < 8; kk++) {
            ulonglong2 A0 = *(const ulonglong2*)&As[buf][kk][wy * 16 + 0];
            ulonglong2 A1 = *(const ulonglong2*)&As[buf][kk][wy * 16 + 4];
            ulonglong2 A2 = *(const ulonglong2*)&As[buf][kk][wy * 16 + 8];
            ulonglong2 A3 = *(const ulonglong2*)&As[buf][kk][wy * 16 + 12];
            ull hr[8] = {A0.x, A0.y, A1.x, A1.y, A2.x, A2.y, A3.x, A3.y};
#pragma unroll
            for (int j = 0; j < 4; j++) {
                ull w = Bd[buf][kk][tx + 32 * j];
#pragma unroll
                for (int p = 0; p < 8; p++) acc[p][j] = fma2(hr[p], w, acc[p][j]);
            }
        }
        if (more) sts(buf ^ 1, av, bv);
        __syncthreads();
        buf ^= 1;
    }

#pragma unroll
    for (int p = 0; p < 8; p++) {
        int m = m0 + wy * 16 + 2 * p;
#pragma unroll
        for (int j = 0; j < 4; j++) {
            int n = n0 + tx + 32 * j;
            if (n < Vv) {
                float2 v = upk(acc[p][j]);
                float bo = bout[n];
                if (m < MROWS)     out[1 + (size_t)m * Vv + n]       = v.x + bo;
                if (m + 1 < MROWS) out[1 + (size_t)(m + 1) * Vv + n] = v.y + bo;
            }
        }
    }
}

// ---------------- K5: per-row log-softmax at gt; masked by PAD ----------------
__global__ __launch_bounds__(256) void k_rowloss(const float* __restrict__ out,
                                                 const int* __restrict__ sent) {
    __shared__ float red[256];
    int m = blockIdx.x;
    const float* row = out + 1 + (size_t)m * Vv;
    int tid = threadIdx.x;

    float mx = -3.4e38f;
    for (int v = tid; v < Vv; v += 256) mx = fmaxf(mx, row[v]);
    red[tid] = mx; __syncthreads();
    for (int s = 128; s > 0; s >>= 1) {
        if (tid < s) red[tid] = fmaxf(red[tid], red[tid + s]);
        __syncthreads();
    }
    mx = red[0]; __syncthreads();

    float sm = 0.f;
    for (int v = tid; v < Vv; v += 256) sm += expf(row[v] - mx);
    red[tid] = sm; __syncthreads();
    for (int s = 128; s > 0; s >>= 1) {
        if (tid < s) red[tid] += red[tid + s];
        __syncthreads();
    }

    if (tid == 0) {
        int b = m / 127, t = m - b * 127;
        int gt = sent[b * Tt + t + 1];
        float lp = 0.f;
        if (gt != 0) lp = row[gt] - mx - logf(red[0]);
        g_rowloss[m] = lp;
    }
}

// ---------------- K6: deterministic loss reduction ----------------
__global__ void k_loss(const int* __restrict__ length, float* __restrict__ out) {
    __shared__ float sb[64];
    int b = threadIdx.x;
    float a = 0.f;
    for (int t = 0; t < TM1; t++) a += g_rowloss[b * TM1 + t];
    sb[b] = -a / (float)length[b];
    __syncthreads();
    if (b == 0) {
        float s = 0.f;
        for (int i = 0; i < 64; i++) s += sb[i];
        out[0] = s;
    }
}

// ---------------- host ----------------
extern "C" void kernel_launch(void* const* d_in, const int* in_sizes, int n_in,
                              void* d_out, int out_size) {
    const int*   sent    = (const int*)d_in[0];
    const int*   length  = (const int*)d_in[1];
    const float* wordvec = (const float*)d_in[2];
    const float* wih0    = (const float*)d_in[3];
    const float* whh0    = (const float*)d_in[4];
    const float* b0      = (const float*)d_in[5];
    const float* wih1    = (const float*)d_in[6];
    const float* whh1    = (const float*)d_in[7];
    const float* b1      = (const float*)d_in[8];
    const float* wout    = (const float*)d_in[9];
    const float* bout    = (const float*)d_in[10];
    float* out = (float*)d_out;

    static int smem_set = 0;
    if (!smem_set) {
        cudaFuncSetAttribute(k_rec, cudaFuncAttributeMaxDynamicSharedMemorySize, SMEM_REC);
        smem_set = 1;
    }

    k_init<<<256, 256>>>();
    k_xw<<<dim3(G4 / 128, 64), 256>>>(sent, wordvec, wih0, b0);
    k_rec<<<GRID_REC, 512, SMEM_REC>>>(whh0, wih1, whh1, b1);
    k_logits<<<dim3((Vv + 127) / 128, (MROWS + 127) / 128), 256>>>(wout, bout, out);
    k_rowloss<<<MROWS, 256>>>(out, sent);
    k_loss<<<1, 64>>>(length, out);
}

// round 7
// speedup vs baseline: 1.2941x; 1.1783x over previous
#include <cuda_runtime.h>
#include <math.h>

#define Bz   64
#define Tt   128
#define TM1  127
#define Vv   10000
#define Ee   300
#define Hh   1024
#define G4   4096
#define MROWS (TM1*Bz)   // 8128
#define GRID_REC 128

typedef unsigned long long ull;

// ---------------- scratch (device globals; no allocs allowed) ----------------
__device__ float g_xw[(size_t)MROWS * G4];     // precomputed x@w_ih0 + b0, layout (t,b,4H)
__device__ float g_h1all[(size_t)MROWS * Hh];  // all h1 states, layout (t,b,H)
__device__ float g_h0[2][Bz * Hh];             // ping-pong layer0 h state
__device__ float g_h1[2][Bz * Hh];             // ping-pong layer1 h state
__device__ float g_rowloss[MROWS];
__device__ unsigned g_barcnt;

// ---------------- f32x2 packed-FMA helpers (sm_100+) ----------------
__device__ __forceinline__ ull pk2(float x, float y) {
    ull r; asm("mov.b64 %0, {%1,%2};" : "=l"(r) : "f"(x), "f"(y)); return r;
}
__device__ __forceinline__ ull fma2(ull a, ull b, ull c) {
    ull d; asm("fma.rn.f32x2 %0, %1, %2, %3;" : "=l"(d) : "l"(a), "l"(b), "l"(c)); return d;
}
__device__ __forceinline__ float2 upk(ull v) {
    float2 f; asm("mov.b64 {%0,%1}, %2;" : "=f"(f.x), "=f"(f.y) : "l"(v)); return f;
}
__device__ __forceinline__ float sigf(float x) { return 1.0f / (1.0f + expf(-x)); }

__device__ __forceinline__ unsigned smem_u32(const void* p) {
    unsigned a;
    asm("{ .reg .u64 t; cvta.to.shared.u64 t, %1; cvt.u32.u64 %0, t; }" : "=r"(a) : "l"(p));
    return a;
}
__device__ __forceinline__ void cp16(unsigned dst, const void* src) {
    asm volatile("cp.async.cg.shared.global [%0], [%1], 16;" :: "r"(dst), "l"(src));
}

// grid-wide epoch barrier (all GRID_REC blocks co-resident: 128 <= #SMs)
__device__ __forceinline__ void gbar(unsigned target) {
    __syncthreads();
    if (threadIdx.x == 0) {
        __threadfence();
        atomicAdd(&g_barcnt, 1u);
        unsigned v;
        do {
            asm volatile("ld.acquire.gpu.u32 %0, [%1];" : "=r"(v) : "l"(&g_barcnt));
        } while (v < target);
    }
    __syncthreads();
}

// ---------------- init states ----------------
__global__ void k_init() {
    int i = blockIdx.x * blockDim.x + threadIdx.x;
    if (i < Bz * Hh) {
        g_h0[0][i] = 0.f; g_h1[0][i] = 0.f;
    }
    if (i == 0) g_barcnt = 0u;
}

// ---------------- K2: xW = gather(emb) @ w_ih0 + b0 ----------------
__global__ __launch_bounds__(256) void k_xw(const int* __restrict__ sent,
                                            const float* __restrict__ wordvec,
                                            const float* __restrict__ wih0,
                                            const float* __restrict__ b0) {
    __shared__ float As[8][128];
    __shared__ float Bs[8][128];
    __shared__ int stok[128];

    int tid = threadIdx.x;
    int n0 = blockIdx.x * 128;
    int m0 = blockIdx.y * 128;

    if (tid < 128) {
        int m = m0 + tid;
        int mc = (m < MROWS) ? m : (MROWS - 1);
        int t = mc >> 6, b = mc & 63;
        stok[tid] = sent[b * Tt + t];
    }
    __syncthreads();

    int tx = tid & 15, ty = tid >> 4;
    ull acc[8][4];
#pragma unroll
    for (int i = 0; i < 8; i++)
#pragma unroll
        for (int j = 0; j < 4; j++) acc[i][j] = 0ULL;

    for (int k0 = 0; k0 < Ee; k0 += 8) {
#pragma unroll
        for (int p = 0; p < 4; p++) {
            int idx = tid + p * 256;
            int r = idx & 127, kk = idx >> 7;
            int k = k0 + kk;
            As[kk][r] = (k < Ee) ? wordvec[(size_t)stok[r] * Ee + k] : 0.f;
            Bs[kk][r] = (k < Ee) ? wih0[(size_t)k * G4 + n0 + r] : 0.f;
        }
        __syncthreads();
#pragma unroll
        for (int kk = 0; kk < 8; kk++) {
            ull bf[4];
#pragma unroll
            for (int j = 0; j < 4; j++) bf[j] = *(const ull*)&Bs[kk][32 * j + 2 * tx];
#pragma unroll
            for (int i = 0; i < 8; i++) {
                float a = As[kk][ty + 16 * i];
                ull a2 = pk2(a, a);
#pragma unroll
                for (int j = 0; j < 4; j++) acc[i][j] = fma2(a2, bf[j], acc[i][j]);
            }
        }
        __syncthreads();
    }

#pragma unroll
    for (int i = 0; i < 8; i++) {
        int m = m0 + ty + 16 * i;
        if (m >= MROWS) continue;
        float* orow = g_xw + (size_t)m * G4 + n0;
#pragma unroll
        for (int j = 0; j < 4; j++) {
            float2 v = upk(acc[i][j]);
            int c = 32 * j + 2 * tx;
            orow[c]     = v.x + b0[n0 + c];
            orow[c + 1] = v.y + b0[n0 + c + 1];
        }
    }
}

// ---------------- K3: persistent recurrence, 3 balanced groups ----------------
// Phase p: L0(t=p) and L1(t=p-1). Groups (256 thr each, full K=1024):
//   g0: h0[p-1] x whh0   g1: h0[p-1] x wih1   g2: h1[p-2] x whh1
// g0/g1 share the h0 smem tile (named barrier 1, 512 thr); g2 independent
// (named barrier 2, 256 thr). One __syncthreads + epilogues + gbar per phase.
#define SMEM_REC 100224
__global__ void __launch_bounds__(768) k_rec(const float* __restrict__ whh0,
                                             const float* __restrict__ wih1,
                                             const float* __restrict__ whh1,
                                             const float* __restrict__ b1) {
    extern __shared__ __align__(16) char smem[];
    float (*SHH0)[32][68] = (float (*)[32][68])(smem);                 // 17408
    float (*SHH1)[32][68] = (float (*)[32][68])(smem + 17408);         // 17408
    float (*SW)[2][32][36] = (float (*)[2][32][36])(smem + 34816);     // 27648
    float (*SGD)[64][33]   = (float (*)[64][33])(smem + 62464);        // 25344
    float (*SXW)[32]       = (float (*)[32])(smem + 87808);            // 8192
    float *SC0 = (float*)(smem + 96000);                                // 2048
    float *SC1 = (float*)(smem + 98048);                                // 2048
    float *SB1 = (float*)(smem + 100096);                               // 128

    const int tid = threadIdx.x;
    const int g   = tid >> 8;            // group 0..2
    const int f   = tid & 255;
    const int tx  = f & 15, ty = f >> 4; // compute map: cols 2tx..+1, rows 4ty..+3
    const int j0  = blockIdx.x * 8;

    // h0 fill map (512 threads, 4 floats each)
    const int hb2 = tid & 63, kq2 = (tid >> 6) & 7;
    // h1 fill map (g2's 256 threads, 8 floats each)
    const int hb = f & 63, kq = f >> 6;              // kq 0..3
    // w fill map (per group, 4 floats each)
    const int kkf = f >> 3;
    const int c4  = (f & 7) * 4;
    const int wcol4 = ((c4 >> 3) << 10) + j0 + (c4 & 7);

    const float* wsrc = (g == 0) ? whh0 : (g == 1) ? wih1 : whh1;

    if (tid < 512) { SC0[tid] = 0.f; SC1[tid] = 0.f; }
    if (tid < 32) SB1[tid] = b1[((tid >> 3) << 10) + j0 + (tid & 7)];
    __syncthreads();

    const unsigned sxw_base = smem_u32(&SXW[0][0]);

    float4 ph0, ph1, pw;

    auto ld_fill = [&](const float* hsrc, int kb) {
        if (g < 2) {
            ph0 = __ldcg((const float4*)(hsrc + hb2 * Hh + kb + kq2 * 4));
        } else {
            ph0 = __ldcg((const float4*)(hsrc + hb * Hh + kb + kq * 4));
            ph1 = __ldcg((const float4*)(hsrc + hb * Hh + kb + kq * 4 + 16));
        }
        pw = __ldg((const float4*)(wsrc + (size_t)(kb + kkf) * G4 + wcol4));
    };
    auto st_fill = [&](int buf) {
        if (g < 2) {
            float* col = &SHH0[buf][kq2 * 4][hb2];
            col[0]      = ph0.x; col[68]     = ph0.y;
            col[2 * 68] = ph0.z; col[3 * 68] = ph0.w;
        } else {
            float* col = &SHH1[buf][kq * 4][hb];
            col[0]      = ph0.x; col[68]     = ph0.y;
            col[2 * 68] = ph0.z; col[3 * 68] = ph0.w;
            float* col2 = &SHH1[buf][kq * 4 + 16][hb];
            col2[0]      = ph1.x; col2[68]     = ph1.y;
            col2[2 * 68] = ph1.z; col2[3 * 68] = ph1.w;
        }
        *(float4*)&SW[g][buf][kkf][c4] = pw;
    };
    auto barg = [&]() {
        if (g < 2) asm volatile("bar.sync 1, 512;" ::: "memory");
        else       asm volatile("bar.sync 2, 256;" ::: "memory");
    };

    unsigned tgt = 0;

    for (int p = 0; p < 128; p++) {
        const int cur = p & 1, nxt = cur ^ 1;

        // prefetch xw[t=p] slice (64 x 32) via cp.async
        if (tid < 512 && p < 127) {
            int b = tid >> 3, q = tid & 7;
            const float* src = g_xw + ((size_t)p * Bz + b) * G4
                               + ((q >> 1) << 10) + j0 + (q & 1) * 4;
            cp16(sxw_base + (unsigned)(b * 32 + q * 4) * 4u, src);
            asm volatile("cp.async.commit_group;");
        }

        const float* hsrc = (g == 2) ? g_h1[nxt] : g_h0[cur];

        ull a0 = 0, a1 = 0, a2 = 0, a3 = 0;

        ld_fill(hsrc, 0);
        st_fill(0);
        barg();

        int buf = 0;
        for (int c = 0; c < 32; c++) {
            if (c < 31) ld_fill(hsrc, (c + 1) * 32);
            {
                const float* hbse = (g < 2) ? &SHH0[buf][0][0] : &SHH1[buf][0][0];
                const float* wbse = &SW[g][buf][0][0];
#pragma unroll
                for (int kk = 0; kk < 32; kk++) {
                    ulonglong2 hA = *(const ulonglong2*)(hbse + kk * 68 + 4 * ty);
                    float2 w2     = *(const float2*)(wbse + kk * 36 + 2 * tx);
                    ull w0 = pk2(w2.x, w2.x);
                    ull w1 = pk2(w2.y, w2.y);
                    a0 = fma2(hA.x, w0, a0);
                    a1 = fma2(hA.y, w0, a1);
                    a2 = fma2(hA.x, w1, a2);
                    a3 = fma2(hA.y, w1, a3);
                }
            }
            if (c < 31) st_fill(buf ^ 1);
            barg();
            buf ^= 1;
        }

        // stage gate partials
        {
            float2 v;
            v = upk(a0); SGD[g][4*ty+0][2*tx]   = v.x; SGD[g][4*ty+1][2*tx]   = v.y;
            v = upk(a1); SGD[g][4*ty+2][2*tx]   = v.x; SGD[g][4*ty+3][2*tx]   = v.y;
            v = upk(a2); SGD[g][4*ty+0][2*tx+1] = v.x; SGD[g][4*ty+1][2*tx+1] = v.y;
            v = upk(a3); SGD[g][4*ty+2][2*tx+1] = v.x; SGD[g][4*ty+3][2*tx+1] = v.y;
        }
        if (tid < 512 && p < 127) asm volatile("cp.async.wait_group 0;");
        __syncthreads();

        if (g == 0) {
            if (p < 127) {
#pragma unroll
                for (int e = 0; e < 2; e++) {
                    int idx = f + 256 * e;
                    int bb = idx & 63, jj = idx >> 6;
                    float iv = SGD[0][bb][jj]      + SXW[bb][jj];
                    float fv = SGD[0][bb][8 + jj]  + SXW[bb][8 + jj];
                    float gv = SGD[0][bb][16 + jj] + SXW[bb][16 + jj];
                    float ov = SGD[0][bb][24 + jj] + SXW[bb][24 + jj];
                    float co = SC0[idx];
                    float cn = sigf(fv) * co + sigf(iv) * tanhf(gv);
                    float hn = sigf(ov) * tanhf(cn);
                    SC0[idx] = cn;
                    g_h0[nxt][bb * Hh + j0 + jj] = hn;
                }
            }
        } else if (g == 1) {
            if (p > 0) {
                int t = p - 1;
#pragma unroll
                for (int e = 0; e < 2; e++) {
                    int idx = f + 256 * e;
                    int bb = idx & 63, jj = idx >> 6;
                    float iv = SGD[1][bb][jj]      + SGD[2][bb][jj]      + SB1[jj];
                    float fv = SGD[1][bb][8 + jj]  + SGD[2][bb][8 + jj]  + SB1[8 + jj];
                    float gv = SGD[1][bb][16 + jj] + SGD[2][bb][16 + jj] + SB1[16 + jj];
                    float ov = SGD[1][bb][24 + jj] + SGD[2][bb][24 + jj] + SB1[24 + jj];
                    float co = SC1[idx];
                    float cn = sigf(fv) * co + sigf(iv) * tanhf(gv);
                    float hn = sigf(ov) * tanhf(cn);
                    SC1[idx] = cn;
                    g_h1[cur][bb * Hh + j0 + jj] = hn;
                    g_h1all[((size_t)t * Bz + bb) * Hh + j0 + jj] = hn;
                }
            }
        }

        if (p < 127) { tgt += GRID_REC; gbar(tgt); }
    }
}

// ---------------- K4: logits = h1_all @ w_out + b_out (double-buffered) -------
__global__ __launch_bounds__(256, 2) void k_logits(const float* __restrict__ wout,
                                                   const float* __restrict__ bout,
                                                   float* __restrict__ out) {
    __shared__ __align__(16) float As[2][8][132];
    __shared__ __align__(16) ull   Bd[2][8][128];
    __shared__ int aoff[128];

    int tid = threadIdx.x;
    int n0 = blockIdx.x * 128;
    int m0 = blockIdx.y * 128;

    if (tid < 128) {
        int m = m0 + tid;
        int mc = (m < MROWS) ? m : (MROWS - 1);
        int b = mc / 127, t = mc - b * 127;
        aoff[tid] = t * Bz + b;
    }
    __syncthreads();

    int tx = tid & 31, wy = tid >> 5;
    int ar = tid >> 1, akq = tid & 1;
    int bkk = tid >> 5, bc = (tid & 31) * 4;
    bool bok = (n0 + bc + 3 < Vv);

    ull acc[8][4];
#pragma unroll
    for (int p = 0; p < 8; p++)
#pragma unroll
        for (int j = 0; j < 4; j++) acc[p][j] = 0ULL;

    auto ldA = [&](int k0) -> float4 {
        return __ldg((const float4*)(g_h1all + (size_t)aoff[ar] * Hh + k0 + akq * 4));
    };
    auto ldB = [&](int k0) -> float4 {
        float4 bv = make_float4(0.f, 0.f, 0.f, 0.f);
        if (bok) {
            bv = __ldg((const float4*)(wout + (size_t)(k0 + bkk) * Vv + n0 + bc));
        } else {
            const float* wr = wout + (size_t)(k0 + bkk) * Vv;
            if (n0 + bc + 0 < Vv) bv.x = wr[n0 + bc + 0];
            if (n0 + bc + 1 < Vv) bv.y = wr[n0 + bc + 1];
            if (n0 + bc + 2 < Vv) bv.z = wr[n0 + bc + 2];
            if (n0 + bc + 3 < Vv) bv.w = wr[n0 + bc + 3];
        }
        return bv;
    };
    auto sts = [&](int bf, float4 av, float4 bv) {
        As[bf][akq * 4 + 0][ar] = av.x; As[bf][akq * 4 + 1][ar] = av.y;
        As[bf][akq * 4 + 2][ar] = av.z; As[bf][akq * 4 + 3][ar] = av.w;
        Bd[bf][bkk][bc + 0] = pk2(bv.x, bv.x); Bd[bf][bkk][bc + 1] = pk2(bv.y, bv.y);
        Bd[bf][bkk][bc + 2] = pk2(bv.z, bv.z); Bd[bf][bkk][bc + 3] = pk2(bv.w, bv.w);
    };

    float4 av = ldA(0), bv = ldB(0);
    sts(0, av, bv);
    __syncthreads();
    int buf = 0;

    for (int k0 = 0; k0 < Hh; k0 += 8) {
        bool more = (k0 + 8 < Hh);
        if (more) { av = ldA(k0 + 8); bv = ldB(k0 + 8); }
#pragma unroll
        for (int kk = 0; kk < 8; kk++) {
            ulonglong2 A0 = *(const ulonglong2*)&As[buf][kk][wy * 16 + 0];
            ulonglong2 A1 = *(const ulonglong2*)&As[buf][kk][wy * 16 + 4];
            ulonglong2 A2 = *(const ulonglong2*)&As[buf][kk][wy * 16 + 8];
            ulonglong2 A3 = *(const ulonglong2*)&As[buf][kk][wy * 16 + 12];
            ull hr[8] = {A0.x, A0.y, A1.x, A1.y, A2.x, A2.y, A3.x, A3.y};
#pragma unroll
            for (int j = 0; j < 4; j++) {
                ull w = Bd[buf][kk][tx + 32 * j];
#pragma unroll
                for (int p = 0; p < 8; p++) acc[p][j] = fma2(hr[p], w, acc[p][j]);
            }
        }
        if (more) sts(buf ^ 1, av, bv);
        __syncthreads();
        buf ^= 1;
    }

#pragma unroll
    for (int p = 0; p < 8; p++) {
        int m = m0 + wy * 16 + 2 * p;
#pragma unroll
        for (int j = 0; j < 4; j++) {
            int n = n0 + tx + 32 * j;
            if (n < Vv) {
                float2 v = upk(acc[p][j]);
                float bo = bout[n];
                if (m < MROWS)     out[1 + (size_t)m * Vv + n]       = v.x + bo;
                if (m + 1 < MROWS) out[1 + (size_t)(m + 1) * Vv + n] = v.y + bo;
            }
        }
    }
}

// ---------------- K5: per-row log-softmax at gt; masked by PAD ----------------
__global__ __launch_bounds__(256) void k_rowloss(const float* __restrict__ out,
                                                 const int* __restrict__ sent) {
    __shared__ float red[256];
    int m = blockIdx.x;
    const float* row = out + 1 + (size_t)m * Vv;
    int tid = threadIdx.x;

    float mx = -3.4e38f;
    for (int v = tid; v < Vv; v += 256) mx = fmaxf(mx, row[v]);
    red[tid] = mx; __syncthreads();
    for (int s = 128; s > 0; s >>= 1) {
        if (tid < s) red[tid] = fmaxf(red[tid], red[tid + s]);
        __syncthreads();
    }
    mx = red[0]; __syncthreads();

    float sm = 0.f;
    for (int v = tid; v < Vv; v += 256) sm += expf(row[v] - mx);
    red[tid] = sm; __syncthreads();
    for (int s = 128; s > 0; s >>= 1) {
        if (tid < s) red[tid] += red[tid + s];
        __syncthreads();
    }

    if (tid == 0) {
        int b = m / 127, t = m - b * 127;
        int gt = sent[b * Tt + t + 1];
        float lp = 0.f;
        if (gt != 0) lp = row[gt] - mx - logf(red[0]);
        g_rowloss[m] = lp;
    }
}

// ---------------- K6: deterministic loss reduction ----------------
__global__ void k_loss(const int* __restrict__ length, float* __restrict__ out) {
    __shared__ float sb[64];
    int b = threadIdx.x;
    float a = 0.f;
    for (int t = 0; t < TM1; t++) a += g_rowloss[b * TM1 + t];
    sb[b] = -a / (float)length[b];
    __syncthreads();
    if (b == 0) {
        float s = 0.f;
        for (int i = 0; i < 64; i++) s += sb[i];
        out[0] = s;
    }
}

// ---------------- host ----------------
extern "C" void kernel_launch(void* const* d_in, const int* in_sizes, int n_in,
                              void* d_out, int out_size) {
    const int*   sent    = (const int*)d_in[0];
    const int*   length  = (const int*)d_in[1];
    const float* wordvec = (const float*)d_in[2];
    const float* wih0    = (const float*)d_in[3];
    const float* whh0    = (const float*)d_in[4];
    const float* b0      = (const float*)d_in[5];
    const float* wih1    = (const float*)d_in[6];
    const float* whh1    = (const float*)d_in[7];
    const float* b1      = (const float*)d_in[8];
    const float* wout    = (const float*)d_in[9];
    const float* bout    = (const float*)d_in[10];
    float* out = (float*)d_out;

    static int smem_set = 0;
    if (!smem_set) {
        cudaFuncSetAttribute(k_rec, cudaFuncAttributeMaxDynamicSharedMemorySize, SMEM_REC);
        smem_set = 1;
    }

    k_init<<<256, 256>>>();
    k_xw<<<dim3(G4 / 128, 64), 256>>>(sent, wordvec, wih0, b0);
    k_rec<<<GRID_REC, 768, SMEM_REC>>>(whh0, wih1, whh1, b1);
    k_logits<<<dim3((Vv + 127) / 128, (MROWS + 127) / 128), 256>>>(wout, bout, out);
    k_rowloss<<<MROWS, 256>>>(out, sent);
    k_loss<<<1, 64>>>(length, out);
}